// round 2
// baseline (speedup 1.0000x reference)
#include <cuda_runtime.h>

#define BATCH 16
#define NPRI  3000
#define NCLS  201
#define CM1   200
#define NCAND (NPRI * CM1)     /* 600000 flat candidates per image */
#define TOPN  100
#define SCORE_THRESH 0.02f
#define NMS_THRESH   0.45f
#define NMS_THREADS  1024

/* ---- scratch (static device globals; no runtime allocation) ---- */
__device__ float2   g_cand[BATCH * NCAND];  /* (score, flat-index bits) */
__device__ int      g_count[BATCH];
__device__ unsigned g_maxbits[BATCH];       /* monotone-encoded float max */
__device__ float4   g_decoded[BATCH * NPRI];

/* monotone uint encoding of float for atomicMax (handles negatives) */
__device__ __forceinline__ unsigned fenc(float f) {
    unsigned u = __float_as_uint(f);
    return (u & 0x80000000u) ? ~u : (u | 0x80000000u);
}
__device__ __forceinline__ float fdec(unsigned e) {
    unsigned u = (e & 0x80000000u) ? (e & 0x7fffffffu) : ~e;
    return __uint_as_float(u);
}

__global__ void init_kernel() {
    int t = threadIdx.x;
    if (t < BATCH) { g_count[t] = 0; g_maxbits[t] = 0u; }
}

/* grid (NPRI/8, BATCH), block 256: one warp handles one (image, prior) row */
__global__ void stage_a(const float* __restrict__ deltas,
                        const float* __restrict__ obj,
                        const float* __restrict__ priors) {
    const int lane = threadIdx.x & 31;
    const int wid  = threadIdx.x >> 5;
    const int p    = blockIdx.x * 8 + wid;
    const int b    = blockIdx.y;
    const long row = (long)b * NPRI + p;
    const float* o = obj + row * NCLS;

    /* softmax over 201 classes (max-subtracted, like jax.nn.softmax) */
    float v[7];
    float m = -3.4e38f;
#pragma unroll
    for (int k = 0; k < 7; k++) {
        int c = lane + 32 * k;
        v[k] = (c < NCLS) ? o[c] : -3.4e38f;
        m = fmaxf(m, v[k]);
    }
#pragma unroll
    for (int d = 16; d; d >>= 1) m = fmaxf(m, __shfl_xor_sync(0xffffffffu, m, d));
    float e[7]; float sum = 0.f;
#pragma unroll
    for (int k = 0; k < 7; k++) {
        int c = lane + 32 * k;
        e[k] = (c < NCLS) ? expf(v[k] - m) : 0.f;
        sum += e[k];
    }
#pragma unroll
    for (int d = 16; d; d >>= 1) sum += __shfl_xor_sync(0xffffffffu, sum, d);

    /* threshold + warp-aggregated compaction (classes 1..200) */
    float prob[7]; int pass[7]; int cnt = 0;
#pragma unroll
    for (int k = 0; k < 7; k++) {
        int c = lane + 32 * k;
        prob[k] = e[k] / sum;
        pass[k] = (c >= 1 && c < NCLS && prob[k] > SCORE_THRESH) ? 1 : 0;
        cnt += pass[k];
    }
    int inc = cnt;
#pragma unroll
    for (int d = 1; d < 32; d <<= 1) {
        int t = __shfl_up_sync(0xffffffffu, inc, d);
        if (lane >= d) inc += t;
    }
    int total = __shfl_sync(0xffffffffu, inc, 31);
    int excl  = inc - cnt;
    int base  = 0;
    if (lane == 0 && total > 0) base = atomicAdd(&g_count[b], total);
    base = __shfl_sync(0xffffffffu, base, 0);
    float2* cd = g_cand + (long)b * NCAND;
    int w = base + excl;
#pragma unroll
    for (int k = 0; k < 7; k++) {
        if (pass[k]) {
            int c = lane + 32 * k;
            cd[w] = make_float2(prob[k], __int_as_float(p * CM1 + (c - 1)));
            w++;
        }
    }

    /* box decode + per-image coordinate max (lane 0) */
    if (lane == 0) {
        const float* dl = deltas + row * 4;
        const float* pr = priors + (long)p * 4;
        float pw = pr[2], ph = pr[3];
        float cx = dl[0] * 0.1f * pw + pr[0];
        float cy = dl[1] * 0.1f * ph + pr[1];
        float bw = expf(dl[2] * 0.2f) * pw;
        float bh = expf(dl[3] * 0.2f) * ph;
        float x1 = cx - 0.5f * bw, y1 = cy - 0.5f * bh;
        float x2 = cx + 0.5f * bw, y2 = cy + 0.5f * bh;
        g_decoded[row] = make_float4(x1, y1, x2, y2);
        float mm = fmaxf(fmaxf(x1, y1), fmaxf(x2, y2));
        atomicMax(&g_maxbits[b], fenc(mm));
    }
}

/* one block per image; 100 sequential greedy-NMS picks */
__global__ void __launch_bounds__(NMS_THREADS) nms_kernel(float* __restrict__ out) {
    const int b   = blockIdx.x;
    const int tid = threadIdx.x;

    __shared__ float4 sbox[NPRI];          /* 48 KB decoded boxes */
    __shared__ float  rs[32];
    __shared__ int    ri[32];
    __shared__ int    rp[32];
    __shared__ float  bc[6];               /* valid, bx1,by1,bx2,by2, barea */

    for (int i = tid; i < NPRI; i += NMS_THREADS)
        sbox[i] = g_decoded[b * NPRI + i];
    const float off = fdec(g_maxbits[b]) + 1.0f;
    const int   n   = g_count[b];
    float2* cd = g_cand + (long)b * NCAND;
    __syncthreads();

    for (int it = 0; it < TOPN; it++) {
        /* ---- global argmax (first-index tie-break, like jnp.argmax) ---- */
        float bs = -2.f; int bi = 0x7fffffff; int bp = -1;
        for (int j = tid; j < n; j += NMS_THREADS) {
            float2 c = cd[j];
            int idx = __float_as_int(c.y);
            if (c.x > bs || (c.x == bs && idx < bi)) { bs = c.x; bi = idx; bp = j; }
        }
#pragma unroll
        for (int d = 16; d; d >>= 1) {
            float os = __shfl_xor_sync(0xffffffffu, bs, d);
            int   oi = __shfl_xor_sync(0xffffffffu, bi, d);
            int   op = __shfl_xor_sync(0xffffffffu, bp, d);
            if (os > bs || (os == bs && oi < bi)) { bs = os; bi = oi; bp = op; }
        }
        if ((tid & 31) == 0) { rs[tid >> 5] = bs; ri[tid >> 5] = bi; rp[tid >> 5] = bp; }
        __syncthreads();
        if (tid == 0) {
            for (int k = 1; k < 32; k++)
                if (rs[k] > bs || (rs[k] == bs && ri[k] < bi)) { bs = rs[k]; bi = ri[k]; bp = rp[k]; }
            float* orow = out + ((long)b * TOPN + it) * 6;
            if (bs > SCORE_THRESH) {
                int pr  = bi / CM1;
                int lab = bi - pr * CM1 + 1;
                float4 d = sbox[pr];
                float shift = (float)lab * off;
                float x1 = d.x + shift, y1 = d.y + shift;
                float x2 = d.z + shift, y2 = d.w + shift;
                bc[0] = 1.f; bc[1] = x1; bc[2] = y1; bc[3] = x2; bc[4] = y2;
                bc[5] = (x2 - x1) * (y2 - y1);
                orow[0] = fminf(fmaxf(d.x, 0.f), 1.f);
                orow[1] = fminf(fmaxf(d.y, 0.f), 1.f);
                orow[2] = fminf(fmaxf(d.z, 0.f), 1.f);
                orow[3] = fminf(fmaxf(d.w, 0.f), 1.f);
                orow[4] = bs;
                orow[5] = (float)lab;
                cd[bp].x = -1.0f;          /* s.at[i].set(-1) */
            } else {
                bc[0] = 0.f;
                orow[0] = orow[1] = orow[2] = orow[3] = orow[4] = orow[5] = 0.f;
            }
        }
        __syncthreads();

        /* ---- suppression pass (offset-box IoU, all classes) ---- */
        if (bc[0] != 0.f) {
            const float bx1 = bc[1], by1 = bc[2], bx2 = bc[3], by2 = bc[4], ba = bc[5];
            for (int j = tid; j < n; j += NMS_THREADS) {
                float2 c = cd[j];
                if (c.x < 0.f) continue;   /* already dead */
                int idx = __float_as_int(c.y);
                int pr  = idx / CM1;
                int lab = idx - pr * CM1 + 1;
                float4 d = sbox[pr];
                float shift = (float)lab * off;
                float x1 = d.x + shift, y1 = d.y + shift;
                float x2 = d.z + shift, y2 = d.w + shift;
                float ix1 = fmaxf(x1, bx1), iy1 = fmaxf(y1, by1);
                float ix2 = fminf(x2, bx2), iy2 = fminf(y2, by2);
                float inter = fmaxf(ix2 - ix1, 0.f) * fmaxf(iy2 - iy1, 0.f);
                float ar    = (x2 - x1) * (y2 - y1);
                float iou   = inter / (ar + ba - inter);
                if (iou > NMS_THRESH) cd[j].x = -1.0f;
            }
        }
        __syncthreads();
    }
}

extern "C" void kernel_launch(void* const* d_in, const int* in_sizes, int n_in,
                              void* d_out, int out_size) {
    const float *deltas = nullptr, *obj = nullptr, *priors = nullptr;
    for (int i = 0; i < n_in; i++) {
        if      (in_sizes[i] == BATCH * NPRI * 4)    deltas = (const float*)d_in[i];
        else if (in_sizes[i] == BATCH * NPRI * NCLS) obj    = (const float*)d_in[i];
        else if (in_sizes[i] == NPRI * 4)            priors = (const float*)d_in[i];
    }
    init_kernel<<<1, 32>>>();
    dim3 g(NPRI / 8, BATCH);
    stage_a<<<g, 256>>>(deltas, obj, priors);
    nms_kernel<<<BATCH, NMS_THREADS>>>((float*)d_out);
}

// round 3
// speedup vs baseline: 5.1446x; 5.1446x over previous
#include <cuda_runtime.h>

typedef unsigned long long u64;
typedef unsigned int u32;

#define BATCH 16
#define NPRI  3000
#define NCLS  201
#define CM1   200
#define NCAND (NPRI * CM1)
#define TOPN  100
#define SCORE_THRESH 0.02f
#define NMS_THRESH   0.45f
#define CAP   22000
#define NTHR  1024

/* ---- static device scratch (no runtime allocation) ---- */
__device__ u64    g_keys[(long)BATCH * NCAND];
__device__ int    g_count[BATCH];
__device__ u32    g_maxbits[BATCH];
__device__ u32    g_minbits[BATCH];
__device__ int    g_hist[BATCH * 256];
__device__ float4 g_decoded[BATCH * NPRI];

__device__ __forceinline__ u64 umax64(u64 a, u64 b) { return a > b ? a : b; }

/* monotone uint encoding of float (handles negatives) for atomicMax/Min */
__device__ __forceinline__ unsigned fenc(float f) {
    unsigned u = __float_as_uint(f);
    return (u & 0x80000000u) ? ~u : (u | 0x80000000u);
}
__device__ __forceinline__ float fdec(unsigned e) {
    unsigned u = (e & 0x80000000u) ? (e & 0x7fffffffu) : ~e;
    return __uint_as_float(u);
}

__global__ void init_kernel() {
    int t = threadIdx.x;
    for (int i = t; i < BATCH * 256; i += NTHR) g_hist[i] = 0;
    if (t < BATCH) { g_count[t] = 0; g_maxbits[t] = 0u; g_minbits[t] = 0xFFFFFFFFu; }
}

/* grid (NPRI/8, BATCH), block 256: one warp per (image, prior) row */
__global__ void stage_a(const float* __restrict__ deltas,
                        const float* __restrict__ obj,
                        const float* __restrict__ priors) {
    const int lane = threadIdx.x & 31;
    const int wid  = threadIdx.x >> 5;
    const int p    = blockIdx.x * 8 + wid;
    const int b    = blockIdx.y;
    const long row = (long)b * NPRI + p;
    const float* o = obj + row * NCLS;

    /* softmax over 201 classes */
    float v[7];
    float m = -3.4e38f;
#pragma unroll
    for (int k = 0; k < 7; k++) {
        int c = lane + 32 * k;
        v[k] = (c < NCLS) ? o[c] : -3.4e38f;
        m = fmaxf(m, v[k]);
    }
#pragma unroll
    for (int d = 16; d; d >>= 1) m = fmaxf(m, __shfl_xor_sync(0xffffffffu, m, d));
    float e[7]; float sum = 0.f;
#pragma unroll
    for (int k = 0; k < 7; k++) {
        int c = lane + 32 * k;
        e[k] = (c < NCLS) ? expf(v[k] - m) : 0.f;
        sum += e[k];
    }
#pragma unroll
    for (int d = 16; d; d >>= 1) sum += __shfl_xor_sync(0xffffffffu, sum, d);

    /* threshold + warp-aggregated compaction (classes 1..200) */
    float prob[7]; int pass[7]; int cnt = 0;
#pragma unroll
    for (int k = 0; k < 7; k++) {
        int c = lane + 32 * k;
        prob[k] = __fdiv_rn(e[k], sum);
        pass[k] = (c >= 1 && c < NCLS && prob[k] > SCORE_THRESH) ? 1 : 0;
        cnt += pass[k];
    }
    int inc = cnt;
#pragma unroll
    for (int d = 1; d < 32; d <<= 1) {
        int t = __shfl_up_sync(0xffffffffu, inc, d);
        if (lane >= d) inc += t;
    }
    int total = __shfl_sync(0xffffffffu, inc, 31);
    int excl  = inc - cnt;
    int base  = 0;
    if (lane == 0 && total > 0) base = atomicAdd(&g_count[b], total);
    base = __shfl_sync(0xffffffffu, base, 0);
    u64* kd = g_keys + (long)b * NCAND;
    int w = base + excl;
#pragma unroll
    for (int k = 0; k < 7; k++) {
        if (pass[k]) {
            int c = lane + 32 * k;
            u32 pk = ((u32)p << 8) | (u32)(c - 1);
            kd[w] = ((u64)__float_as_uint(prob[k]) << 32) | (u32)(~pk);
            atomicAdd(&g_hist[b * 256 + (c - 1)], 1);
            w++;
        }
    }

    /* box decode + per-image coord max/min (lane 0) */
    if (lane == 0) {
        const float* dl = deltas + row * 4;
        const float* pr = priors + (long)p * 4;
        float pw = pr[2], ph = pr[3];
        float cx = dl[0] * 0.1f * pw + pr[0];
        float cy = dl[1] * 0.1f * ph + pr[1];
        float bw = expf(dl[2] * 0.2f) * pw;
        float bh = expf(dl[3] * 0.2f) * ph;
        float x1 = cx - 0.5f * bw, y1 = cy - 0.5f * bh;
        float x2 = cx + 0.5f * bw, y2 = cy + 0.5f * bh;
        g_decoded[row] = make_float4(x1, y1, x2, y2);
        float mm = fmaxf(fmaxf(x1, y1), fmaxf(x2, y2));
        float mn = fminf(fminf(x1, y1), fminf(x2, y2));
        atomicMax(&g_maxbits[b], fenc(mm));
        atomicMin(&g_minbits[b], fenc(mn));
    }
}

struct Sm {
    float4 sbox[NPRI];      /* 48 KB decoded boxes */
    u64    keys[CAP];       /* candidate keys (grouped by label on fast path) */
    u64    lmaxs[CM1];      /* per-label live max */
    u64    red[32];         /* fallback reduction */
    float  fbc[8];          /* fallback broadcast: picked shifted box + area */
    int    flag[1];
    int    seg[CM1 + 1];
    int    cur[CM1];
    int    hsh[CM1];
};

__global__ void __launch_bounds__(NTHR) nms_kernel(float* __restrict__ out) {
    extern __shared__ char smraw[];
    Sm* sm = (Sm*)smraw;
    const int b   = blockIdx.x;
    const int tid = threadIdx.x;
    const int wid = tid >> 5, lane = tid & 31;

    const int   n    = g_count[b];
    const float off  = fdec(g_maxbits[b]) + 1.0f;
    const float minv = fdec(g_minbits[b]);
    const bool  fast = (n <= CAP) && (minv > -1.0f);

    for (int i = tid; i < NPRI; i += NTHR)
        sm->sbox[i] = g_decoded[b * NPRI + i];

    if (fast) {
        /* ---- group candidates by label in smem ---- */
        for (int l = tid; l < CM1; l += NTHR) { sm->hsh[l] = g_hist[b * 256 + l]; sm->cur[l] = 0; }
        __syncthreads();
        if (tid == 0) {
            int s = 0;
            for (int l = 0; l < CM1; l++) { sm->seg[l] = s; s += sm->hsh[l]; }
            sm->seg[CM1] = s;
        }
        __syncthreads();
        const u64* gk = g_keys + (long)b * NCAND;
        for (int j = tid; j < n; j += NTHR) {
            u64 k = gk[j];
            int labf = (int)((~(u32)k) & 255u);
            int pos  = sm->seg[labf] + atomicAdd(&sm->cur[labf], 1);
            sm->keys[pos] = k;
        }
        __syncthreads();
        /* ---- init per-label maxes (all 32 warps) ---- */
        for (int l = wid; l < CM1; l += 32) {
            int s0 = sm->seg[l], s1 = sm->seg[l + 1];
            u64 mx = 0;
            for (int j = s0 + lane; j < s1; j += 32) mx = umax64(mx, sm->keys[j]);
#pragma unroll
            for (int d = 16; d; d >>= 1) mx = umax64(mx, __shfl_xor_sync(0xffffffffu, mx, d));
            if (lane == 0) sm->lmaxs[l] = mx;
        }
        __syncthreads();

        /* ---- 100 greedy picks, single warp, all state in regs/smem ---- */
        if (wid == 0) {
            u64 lm[7];
#pragma unroll
            for (int s = 0; s < 7; s++) {
                int l = lane + 32 * s;
                lm[s] = (l < CM1) ? sm->lmaxs[l] : 0ULL;
            }
            u64 mymax = 0;
#pragma unroll
            for (int s = 0; s < 7; s++) mymax = umax64(mymax, lm[s]);

            for (int it = 0; it < TOPN; it++) {
                u64 bk = mymax;
#pragma unroll
                for (int d = 16; d; d >>= 1) bk = umax64(bk, __shfl_xor_sync(0xffffffffu, bk, d));
                if (bk == 0ULL) {               /* nothing live -> zero fill rest */
                    for (int q = it * 6 + lane; q < TOPN * 6; q += 32)
                        out[(long)b * TOPN * 6 + q] = 0.f;
                    break;
                }
                u32 pk   = ~(u32)bk;
                int pr   = (int)(pk >> 8);
                int labf = (int)(pk & 255u);
                float sc = __uint_as_float((u32)(bk >> 32));
                float4 d4 = sm->sbox[pr];
                float shift = __fmul_rn((float)(labf + 1), off);
                float px1 = __fadd_rn(d4.x, shift), py1 = __fadd_rn(d4.y, shift);
                float px2 = __fadd_rn(d4.z, shift), py2 = __fadd_rn(d4.w, shift);
                float pare = __fmul_rn(__fsub_rn(px2, px1), __fsub_rn(py2, py1));
                if (lane == 0) {
                    float* orow = out + ((long)b * TOPN + it) * 6;
                    orow[0] = fminf(fmaxf(d4.x, 0.f), 1.f);
                    orow[1] = fminf(fmaxf(d4.y, 0.f), 1.f);
                    orow[2] = fminf(fmaxf(d4.z, 0.f), 1.f);
                    orow[3] = fminf(fmaxf(d4.w, 0.f), 1.f);
                    orow[4] = sc;
                    orow[5] = (float)(labf + 1);
                }
                /* suppress within this label's segment, recompute its max */
                int s0 = sm->seg[labf], s1 = sm->seg[labf + 1];
                u64 nm = 0;
                for (int j = s0 + lane; j < s1; j += 32) {
                    u64 k = sm->keys[j];
                    if (!k) continue;
                    u32 pk2 = ~(u32)k;
                    float4 c4 = sm->sbox[pk2 >> 8];
                    float x1 = __fadd_rn(c4.x, shift), y1 = __fadd_rn(c4.y, shift);
                    float x2 = __fadd_rn(c4.z, shift), y2 = __fadd_rn(c4.w, shift);
                    float ix1 = fmaxf(x1, px1), iy1 = fmaxf(y1, py1);
                    float ix2 = fminf(x2, px2), iy2 = fminf(y2, py2);
                    float inter = __fmul_rn(fmaxf(__fsub_rn(ix2, ix1), 0.f),
                                            fmaxf(__fsub_rn(iy2, iy1), 0.f));
                    float ar  = __fmul_rn(__fsub_rn(x2, x1), __fsub_rn(y2, y1));
                    float iou = __fdiv_rn(inter, __fsub_rn(__fadd_rn(ar, pare), inter));
                    if (iou > NMS_THRESH) sm->keys[j] = 0ULL;  /* pick self-kills: iou=1 */
                    else nm = umax64(nm, k);
                }
#pragma unroll
                for (int d = 16; d; d >>= 1) nm = umax64(nm, __shfl_xor_sync(0xffffffffu, nm, d));
                if (lane == (labf & 31)) {
                    lm[labf >> 5] = nm;
                    mymax = 0;
#pragma unroll
                    for (int s = 0; s < 7; s++) mymax = umax64(mymax, lm[s]);
                }
            }
        }
    } else {
        /* ---- exact fallback: flat rescan with per-candidate offsets ---- */
        u64* kp;
        if (n <= CAP) {
            const u64* gk = g_keys + (long)b * NCAND;
            for (int j = tid; j < n; j += NTHR) sm->keys[j] = gk[j];
            kp = sm->keys;
        } else {
            kp = g_keys + (long)b * NCAND;
        }
        __syncthreads();
        for (int it = 0; it < TOPN; it++) {
            u64 bk = 0;
            for (int j = tid; j < n; j += NTHR) bk = umax64(bk, kp[j]);
#pragma unroll
            for (int d = 16; d; d >>= 1) bk = umax64(bk, __shfl_xor_sync(0xffffffffu, bk, d));
            if (lane == 0) sm->red[wid] = bk;
            __syncthreads();
            if (tid == 0) {
                for (int k = 1; k < 32; k++) bk = umax64(bk, sm->red[k]);
                float* orow = out + ((long)b * TOPN + it) * 6;
                if (bk != 0ULL) {
                    u32 pk = ~(u32)bk;
                    int pr = (int)(pk >> 8), labf = (int)(pk & 255u);
                    float4 d4 = sm->sbox[pr];
                    float shift = __fmul_rn((float)(labf + 1), off);
                    float px1 = __fadd_rn(d4.x, shift), py1 = __fadd_rn(d4.y, shift);
                    float px2 = __fadd_rn(d4.z, shift), py2 = __fadd_rn(d4.w, shift);
                    sm->fbc[0] = px1; sm->fbc[1] = py1; sm->fbc[2] = px2; sm->fbc[3] = py2;
                    sm->fbc[4] = __fmul_rn(__fsub_rn(px2, px1), __fsub_rn(py2, py1));
                    sm->flag[0] = 1;
                    orow[0] = fminf(fmaxf(d4.x, 0.f), 1.f);
                    orow[1] = fminf(fmaxf(d4.y, 0.f), 1.f);
                    orow[2] = fminf(fmaxf(d4.z, 0.f), 1.f);
                    orow[3] = fminf(fmaxf(d4.w, 0.f), 1.f);
                    orow[4] = __uint_as_float((u32)(bk >> 32));
                    orow[5] = (float)(labf + 1);
                } else {
                    sm->flag[0] = 0;
                    orow[0] = orow[1] = orow[2] = orow[3] = orow[4] = orow[5] = 0.f;
                }
            }
            __syncthreads();
            if (sm->flag[0]) {
                float px1 = sm->fbc[0], py1 = sm->fbc[1];
                float px2 = sm->fbc[2], py2 = sm->fbc[3], pare = sm->fbc[4];
                for (int j = tid; j < n; j += NTHR) {
                    u64 k = kp[j];
                    if (!k) continue;
                    u32 pk2 = ~(u32)k;
                    float4 c4 = sm->sbox[pk2 >> 8];
                    float shift2 = __fmul_rn((float)((pk2 & 255u) + 1), off);
                    float x1 = __fadd_rn(c4.x, shift2), y1 = __fadd_rn(c4.y, shift2);
                    float x2 = __fadd_rn(c4.z, shift2), y2 = __fadd_rn(c4.w, shift2);
                    float ix1 = fmaxf(x1, px1), iy1 = fmaxf(y1, py1);
                    float ix2 = fminf(x2, px2), iy2 = fminf(y2, py2);
                    float inter = __fmul_rn(fmaxf(__fsub_rn(ix2, ix1), 0.f),
                                            fmaxf(__fsub_rn(iy2, iy1), 0.f));
                    float ar  = __fmul_rn(__fsub_rn(x2, x1), __fsub_rn(y2, y1));
                    float iou = __fdiv_rn(inter, __fsub_rn(__fadd_rn(ar, pare), inter));
                    if (iou > NMS_THRESH) kp[j] = 0ULL;
                }
            }
            __syncthreads();
        }
    }
}

extern "C" void kernel_launch(void* const* d_in, const int* in_sizes, int n_in,
                              void* d_out, int out_size) {
    const float *deltas = nullptr, *obj = nullptr, *priors = nullptr;
    for (int i = 0; i < n_in; i++) {
        if      (in_sizes[i] == BATCH * NPRI * 4)    deltas = (const float*)d_in[i];
        else if (in_sizes[i] == BATCH * NPRI * NCLS) obj    = (const float*)d_in[i];
        else if (in_sizes[i] == NPRI * 4)            priors = (const float*)d_in[i];
    }
    cudaFuncSetAttribute(nms_kernel, cudaFuncAttributeMaxDynamicSharedMemorySize,
                         (int)sizeof(Sm));
    init_kernel<<<1, NTHR>>>();
    dim3 g(NPRI / 8, BATCH);
    stage_a<<<g, 256>>>(deltas, obj, priors);
    nms_kernel<<<BATCH, NTHR, sizeof(Sm)>>>((float*)d_out);
}

// round 4
// speedup vs baseline: 5.7292x; 1.1136x over previous
#include <cuda_runtime.h>

typedef unsigned long long u64;
typedef unsigned int u32;

#define BATCH 16
#define NPRI  3000
#define NCLS  201
#define CM1   200
#define NCAND (NPRI * CM1)
#define TOPN  100
#define SCORE_THRESH 0.02f
#define NMS_THRESH   0.45f
#define CAP   22000
#define NTHR  1024

/* ---- static device scratch (zero-initialized at module load; nms_kernel
   restores the zeros at its end so every graph replay sees clean state) ---- */
__device__ u64    g_keys[(long)BATCH * NCAND];
__device__ int    g_count[BATCH];
__device__ u32    g_maxbits[BATCH];   /* max of fenc(coord)  */
__device__ u32    g_minbits[BATCH];   /* max of fenc(-coord) => encodes min */
__device__ int    g_hist[BATCH * 256];
__device__ float4 g_decoded[BATCH * NPRI];

__device__ __forceinline__ u64 umax64(u64 a, u64 b) { return a > b ? a : b; }

/* monotone uint encoding of float (handles negatives) for atomicMax */
__device__ __forceinline__ unsigned fenc(float f) {
    unsigned u = __float_as_uint(f);
    return (u & 0x80000000u) ? ~u : (u | 0x80000000u);
}
__device__ __forceinline__ float fdec(unsigned e) {
    unsigned u = (e & 0x80000000u) ? (e & 0x7fffffffu) : ~e;
    return __uint_as_float(u);
}

/* warp max of u64 key via 2x REDUX: max score word, then max low word
   (low = ~flat_index, so ties resolve to smallest flat index) */
__device__ __forceinline__ u64 wmax64(u64 k) {
    u32 hi = (u32)(k >> 32);
    u32 mh = __reduce_max_sync(0xffffffffu, hi);
    u32 ml = __reduce_max_sync(0xffffffffu, (hi == mh) ? (u32)k : 0u);
    return ((u64)mh << 32) | ml;
}

/* grid (NPRI/8, BATCH), block 256: one warp per (image, prior) row */
__global__ void stage_a(const float* __restrict__ deltas,
                        const float* __restrict__ obj,
                        const float* __restrict__ priors) {
    const int lane = threadIdx.x & 31;
    const int wid  = threadIdx.x >> 5;
    const int p    = blockIdx.x * 8 + wid;
    const int b    = blockIdx.y;
    const long row = (long)b * NPRI + p;
    const float* o = obj + row * NCLS;

    /* softmax over 201 classes */
    float v[7];
    float m = -3.4e38f;
#pragma unroll
    for (int k = 0; k < 7; k++) {
        int c = lane + 32 * k;
        v[k] = (c < NCLS) ? o[c] : -3.4e38f;
        m = fmaxf(m, v[k]);
    }
#pragma unroll
    for (int d = 16; d; d >>= 1) m = fmaxf(m, __shfl_xor_sync(0xffffffffu, m, d));
    float e[7]; float sum = 0.f;
#pragma unroll
    for (int k = 0; k < 7; k++) {
        int c = lane + 32 * k;
        e[k] = (c < NCLS) ? expf(v[k] - m) : 0.f;
        sum += e[k];
    }
#pragma unroll
    for (int d = 16; d; d >>= 1) sum += __shfl_xor_sync(0xffffffffu, sum, d);

    /* threshold + warp-aggregated compaction (classes 1..200) */
    float prob[7]; int pass[7]; int cnt = 0;
#pragma unroll
    for (int k = 0; k < 7; k++) {
        int c = lane + 32 * k;
        prob[k] = __fdiv_rn(e[k], sum);
        pass[k] = (c >= 1 && c < NCLS && prob[k] > SCORE_THRESH) ? 1 : 0;
        cnt += pass[k];
    }
    int inc = cnt;
#pragma unroll
    for (int d = 1; d < 32; d <<= 1) {
        int t = __shfl_up_sync(0xffffffffu, inc, d);
        if (lane >= d) inc += t;
    }
    int total = __shfl_sync(0xffffffffu, inc, 31);
    int excl  = inc - cnt;
    int base  = 0;
    if (lane == 0 && total > 0) base = atomicAdd(&g_count[b], total);
    base = __shfl_sync(0xffffffffu, base, 0);
    u64* kd = g_keys + (long)b * NCAND;
    int w = base + excl;
#pragma unroll
    for (int k = 0; k < 7; k++) {
        if (pass[k]) {
            int c = lane + 32 * k;
            u32 pk = ((u32)p << 8) | (u32)(c - 1);
            kd[w] = ((u64)__float_as_uint(prob[k]) << 32) | (u32)(~pk);
            atomicAdd(&g_hist[b * 256 + (c - 1)], 1);
            w++;
        }
    }

    /* box decode + per-image coord max/min (lane 0) */
    if (lane == 0) {
        const float* dl = deltas + row * 4;
        const float* pr = priors + (long)p * 4;
        float pw = pr[2], ph = pr[3];
        float cx = dl[0] * 0.1f * pw + pr[0];
        float cy = dl[1] * 0.1f * ph + pr[1];
        float bw = expf(dl[2] * 0.2f) * pw;
        float bh = expf(dl[3] * 0.2f) * ph;
        float x1 = cx - 0.5f * bw, y1 = cy - 0.5f * bh;
        float x2 = cx + 0.5f * bw, y2 = cy + 0.5f * bh;
        g_decoded[row] = make_float4(x1, y1, x2, y2);
        float mm = fmaxf(fmaxf(x1, y1), fmaxf(x2, y2));
        float mn = fminf(fminf(x1, y1), fminf(x2, y2));
        atomicMax(&g_maxbits[b], fenc(mm));
        atomicMax(&g_minbits[b], fenc(-mn));
    }
}

struct Sm {
    float4 sbox[NPRI];      /* 48 KB decoded boxes */
    u64    keys[CAP];       /* candidate keys grouped by label */
    u64    lmaxs[CM1];
    u64    red[32];
    float  fbc[8];
    int    flag[1];
    int    seg[CM1 + 1];
    int    cur[CM1];
};

__global__ void __launch_bounds__(NTHR) nms_kernel(float* __restrict__ out) {
    extern __shared__ char smraw[];
    Sm* sm = (Sm*)smraw;
    const int b   = blockIdx.x;
    const int tid = threadIdx.x;
    const int wid = tid >> 5, lane = tid & 31;

    const int   n    = g_count[b];
    const float off  = fdec(g_maxbits[b]) + 1.0f;
    const float minv = -fdec(g_minbits[b]);
    const bool  fast = (n <= CAP) && (minv > -1.0f);

    for (int i = tid; i < NPRI; i += NTHR)
        sm->sbox[i] = g_decoded[b * NPRI + i];

    if (fast) {
        for (int l = tid; l < CM1; l += NTHR) sm->cur[l] = 0;
        /* warp 0: parallel exclusive prefix over the 200-bin histogram */
        if (wid == 0) {
            int carry = 0;
#pragma unroll
            for (int c = 0; c < 7; c++) {
                int l = c * 32 + lane;
                int h = (l < CM1) ? g_hist[b * 256 + l] : 0;
                int v = h;
#pragma unroll
                for (int d = 1; d < 32; d <<= 1) {
                    int t = __shfl_up_sync(0xffffffffu, v, d);
                    if (lane >= d) v += t;
                }
                if (l < CM1) sm->seg[l] = carry + v - h;
                carry += __shfl_sync(0xffffffffu, v, 31);
            }
            if (lane == 0) sm->seg[CM1] = carry;
        }
        __syncthreads();

        /* scatter keys into label-grouped segments */
        const u64* gk = g_keys + (long)b * NCAND;
        for (int j = tid; j < n; j += NTHR) {
            u64 k = gk[j];
            int labf = (int)((~(u32)k) & 255u);
            int pos  = sm->seg[labf] + atomicAdd(&sm->cur[labf], 1);
            sm->keys[pos] = k;
        }
        __syncthreads();

        /* per-label max init */
        for (int l = wid; l < CM1; l += 32) {
            int s0 = sm->seg[l], s1 = sm->seg[l + 1];
            u64 mx = 0;
            for (int j = s0 + lane; j < s1; j += 32) mx = umax64(mx, sm->keys[j]);
            mx = wmax64(mx);
            if (lane == 0) sm->lmaxs[l] = mx;
        }
        __syncthreads();

        /* ---- 100 greedy picks, warp 0 only ---- */
        if (wid == 0) {
            u64 lm[7];
#pragma unroll
            for (int s = 0; s < 7; s++) {
                int l = lane + 32 * s;
                lm[s] = (l < CM1) ? sm->lmaxs[l] : 0ULL;
            }
            u64 mymax = 0;
#pragma unroll
            for (int s = 0; s < 7; s++) mymax = umax64(mymax, lm[s]);

            for (int it = 0; it < TOPN; it++) {
                u64 bk = wmax64(mymax);
                if (bk == 0ULL) {
                    for (int q = it * 6 + lane; q < TOPN * 6; q += 32)
                        out[(long)b * TOPN * 6 + q] = 0.f;
                    break;
                }
                u32 pk   = ~(u32)bk;
                int pr   = (int)(pk >> 8);
                int labf = (int)(pk & 255u);
                float4 d4 = sm->sbox[pr];
                float shift = __fmul_rn((float)(labf + 1), off);
                float px1 = __fadd_rn(d4.x, shift), py1 = __fadd_rn(d4.y, shift);
                float px2 = __fadd_rn(d4.z, shift), py2 = __fadd_rn(d4.w, shift);
                float pare = __fmul_rn(__fsub_rn(px2, px1), __fsub_rn(py2, py1));

                /* suppress within this label's segment, track new max */
                int s0 = sm->seg[labf], s1 = sm->seg[labf + 1];
                u64 nm = 0;
                for (int j = s0 + lane; j < s1; j += 32) {
                    u64 k = sm->keys[j];
                    if (!k) continue;
                    u32 pk2 = ~(u32)k;
                    float4 c4 = sm->sbox[pk2 >> 8];
                    float x1 = __fadd_rn(c4.x, shift), y1 = __fadd_rn(c4.y, shift);
                    float x2 = __fadd_rn(c4.z, shift), y2 = __fadd_rn(c4.w, shift);
                    float ix1 = fmaxf(x1, px1), iy1 = fmaxf(y1, py1);
                    float ix2 = fminf(x2, px2), iy2 = fminf(y2, py2);
                    float inter = __fmul_rn(fmaxf(__fsub_rn(ix2, ix1), 0.f),
                                            fmaxf(__fsub_rn(iy2, iy1), 0.f));
                    float ar  = __fmul_rn(__fsub_rn(x2, x1), __fsub_rn(y2, y1));
                    float iou = __fdiv_rn(inter, __fsub_rn(__fadd_rn(ar, pare), inter));
                    if (iou > NMS_THRESH) sm->keys[j] = 0ULL;  /* pick self-kills */
                    else nm = umax64(nm, k);
                }
                nm = wmax64(nm);

                if (lane == 0) {
                    float* orow = out + ((long)b * TOPN + it) * 6;
                    orow[0] = fminf(fmaxf(d4.x, 0.f), 1.f);
                    orow[1] = fminf(fmaxf(d4.y, 0.f), 1.f);
                    orow[2] = fminf(fmaxf(d4.z, 0.f), 1.f);
                    orow[3] = fminf(fmaxf(d4.w, 0.f), 1.f);
                    orow[4] = __uint_as_float((u32)(bk >> 32));
                    orow[5] = (float)(labf + 1);
                }

                /* owner lane updates its label register (compile-time indexed
                   predicated writes -> stays in registers, no local memory) */
                int sidx = labf >> 5;
                if (lane == (labf & 31)) {
#pragma unroll
                    for (int q = 0; q < 7; q++) if (q == sidx) lm[q] = nm;
                    mymax = 0;
#pragma unroll
                    for (int q = 0; q < 7; q++) mymax = umax64(mymax, lm[q]);
                }
            }
        }
    } else {
        /* ---- exact fallback: flat rescan with per-candidate offsets ---- */
        u64* kp;
        if (n <= CAP) {
            const u64* gk = g_keys + (long)b * NCAND;
            for (int j = tid; j < n; j += NTHR) sm->keys[j] = gk[j];
            kp = sm->keys;
        } else {
            kp = g_keys + (long)b * NCAND;
        }
        __syncthreads();
        for (int it = 0; it < TOPN; it++) {
            u64 bk = 0;
            for (int j = tid; j < n; j += NTHR) bk = umax64(bk, kp[j]);
            bk = wmax64(bk);
            if (lane == 0) sm->red[wid] = bk;
            __syncthreads();
            if (tid == 0) {
                for (int k = 1; k < 32; k++) bk = umax64(bk, sm->red[k]);
                float* orow = out + ((long)b * TOPN + it) * 6;
                if (bk != 0ULL) {
                    u32 pk = ~(u32)bk;
                    int pr = (int)(pk >> 8), labf = (int)(pk & 255u);
                    float4 d4 = sm->sbox[pr];
                    float shift = __fmul_rn((float)(labf + 1), off);
                    float px1 = __fadd_rn(d4.x, shift), py1 = __fadd_rn(d4.y, shift);
                    float px2 = __fadd_rn(d4.z, shift), py2 = __fadd_rn(d4.w, shift);
                    sm->fbc[0] = px1; sm->fbc[1] = py1; sm->fbc[2] = px2; sm->fbc[3] = py2;
                    sm->fbc[4] = __fmul_rn(__fsub_rn(px2, px1), __fsub_rn(py2, py1));
                    sm->flag[0] = 1;
                    orow[0] = fminf(fmaxf(d4.x, 0.f), 1.f);
                    orow[1] = fminf(fmaxf(d4.y, 0.f), 1.f);
                    orow[2] = fminf(fmaxf(d4.z, 0.f), 1.f);
                    orow[3] = fminf(fmaxf(d4.w, 0.f), 1.f);
                    orow[4] = __uint_as_float((u32)(bk >> 32));
                    orow[5] = (float)(labf + 1);
                } else {
                    sm->flag[0] = 0;
                    orow[0] = orow[1] = orow[2] = orow[3] = orow[4] = orow[5] = 0.f;
                }
            }
            __syncthreads();
            if (sm->flag[0]) {
                float px1 = sm->fbc[0], py1 = sm->fbc[1];
                float px2 = sm->fbc[2], py2 = sm->fbc[3], pare = sm->fbc[4];
                for (int j = tid; j < n; j += NTHR) {
                    u64 k = kp[j];
                    if (!k) continue;
                    u32 pk2 = ~(u32)k;
                    float4 c4 = sm->sbox[pk2 >> 8];
                    float shift2 = __fmul_rn((float)((pk2 & 255u) + 1), off);
                    float x1 = __fadd_rn(c4.x, shift2), y1 = __fadd_rn(c4.y, shift2);
                    float x2 = __fadd_rn(c4.z, shift2), y2 = __fadd_rn(c4.w, shift2);
                    float ix1 = fmaxf(x1, px1), iy1 = fmaxf(y1, py1);
                    float ix2 = fminf(x2, px2), iy2 = fminf(y2, py2);
                    float inter = __fmul_rn(fmaxf(__fsub_rn(ix2, ix1), 0.f),
                                            fmaxf(__fsub_rn(iy2, iy1), 0.f));
                    float ar  = __fmul_rn(__fsub_rn(x2, x1), __fsub_rn(y2, y1));
                    float iou = __fdiv_rn(inter, __fsub_rn(__fadd_rn(ar, pare), inter));
                    if (iou > NMS_THRESH) kp[j] = 0ULL;
                }
            }
            __syncthreads();
        }
    }

    /* reset globals to load-time zeros for the next graph replay
       (all values above were consumed before the last __syncthreads /
        by-register at kernel start, so racing warps are safe) */
    for (int l = tid; l < 256; l += NTHR) g_hist[b * 256 + l] = 0;
    if (tid == 0) { g_count[b] = 0; g_maxbits[b] = 0u; g_minbits[b] = 0u; }
}

extern "C" void kernel_launch(void* const* d_in, const int* in_sizes, int n_in,
                              void* d_out, int out_size) {
    const float *deltas = nullptr, *obj = nullptr, *priors = nullptr;
    for (int i = 0; i < n_in; i++) {
        if      (in_sizes[i] == BATCH * NPRI * 4)    deltas = (const float*)d_in[i];
        else if (in_sizes[i] == BATCH * NPRI * NCLS) obj    = (const float*)d_in[i];
        else if (in_sizes[i] == NPRI * 4)            priors = (const float*)d_in[i];
    }
    cudaFuncSetAttribute(nms_kernel, cudaFuncAttributeMaxDynamicSharedMemorySize,
                         (int)sizeof(Sm));
    dim3 g(NPRI / 8, BATCH);
    stage_a<<<g, 256>>>(deltas, obj, priors);
    nms_kernel<<<BATCH, NTHR, sizeof(Sm)>>>((float*)d_out);
}